// round 7
// baseline (speedup 1.0000x reference)
#include <cuda_runtime.h>

#define NS 8
#define NC 128
#define KT 32
#define KF 16
#define FREQ 256
#define NFW 15
#define THR 15.0f
#define LPRE 431
#define NPOT 6400
#define MARGIN 0.05f
#define NCAND 16

#define TP 33
#define RROW_OFF  14224
#define RROW2_OFF 21120
#define S_OFF     28016
#define X2_OFF    34416
#define XP_OFF    40816
#define SMEM_F    41328   /* 165,312 bytes */

__device__ int      g_pool[NS * NFW * NC];
__device__ unsigned g_done;

__global__ __launch_bounds__(512, 1)
void spyke_kernel(const float* __restrict__ X, const float* __restrict__ W,
                  int* __restrict__ out)
{
    extern __shared__ float sm[];
    float* tile   = sm;
    float* Rrow   = sm + RROW_OFF;
    float* Rrow2  = sm + RROW2_OFF;
    float* Sarr   = sm + S_OFF;
    float* X2arr  = sm + X2_OFF;
    float* xpatch = sm + XP_OFF;

    __shared__ unsigned long long s_cand[NCAND];
    __shared__ int s_p[NCAND];
    __shared__ float s_cw[NC], s_cb[NC];
    __shared__ unsigned s_pool[4], s_res[4];
    __shared__ int s_rcnt, s_last, s_any, s_key, s_cfired;
    __shared__ int s_rem[NC];

    const int s = blockIdx.x / NFW, fwin = blockIdx.x % NFW;
    const int tid = threadIdx.x, col0 = fwin * 16, sec = s * 400;

    if (tid < NCAND) s_cand[tid] = 0ULL;
    if (tid < 4) { s_pool[tid] = 0u; s_res[tid] = 0u; }
    if (tid == 0) s_rcnt = 0;

    // ---- stage X window ----
    for (int i = tid; i < LPRE * 31; i += 512) {
        int r = i / 31, c = i - r * 31;
        tile[r * TP + c] = X[(sec + r) * FREQ + col0 + c];
    }
    __syncthreads();

    // ---- row sliding sums/sumsq over kf-window of 16 ----
    if (tid < LPRE) {
        float a = 0.f, a2 = 0.f;
        for (int c = 0; c < 16; ++c) { float x = tile[tid*TP + c]; a += x; a2 += x*x; }
        Rrow[tid*16] = a; Rrow2[tid*16] = a2;
        for (int f = 1; f < 16; ++f) {
            float xo = tile[tid*TP + f - 1], xn = tile[tid*TP + f + 15];
            a += xn - xo; a2 += xn*xn - xo*xo;
            Rrow[tid*16 + f] = a; Rrow2[tid*16 + f] = a2;
        }
    }
    __syncthreads();

    // ---- column sliding over kt-window of 32: S, X2; per-region argmax ----
    if (tid < 320) {
        int f = tid / 20, t0 = (tid % 20) * 20;
        float a = 0.f, a2 = 0.f;
        for (int k = 0; k < 32; ++k) { a += Rrow[(t0+k)*16+f]; a2 += Rrow2[(t0+k)*16+f]; }
        unsigned long long lkey[2] = {0ULL, 0ULL};   // chunk of 20 spans <= 2 regions
        int reg0 = t0 / 25;
        for (int t = t0; t < t0 + 20; ++t) {
            int p = t*16 + f;
            Sarr[p] = a; X2arr[p] = a2;
            unsigned long long key =
                ((unsigned long long)__float_as_uint(a) << 13) | (unsigned)p;
            int ri = (t / 25) - reg0;
            if (key > lkey[ri]) lkey[ri] = key;
            if (t <= 398) {
                a  += Rrow[(t+32)*16+f]  - Rrow[t*16+f];
                a2 += Rrow2[(t+32)*16+f] - Rrow2[t*16+f];
            }
        }
        atomicMax(&s_cand[reg0], lkey[0]);
        if (lkey[1] && reg0 + 1 < NCAND) atomicMax(&s_cand[reg0 + 1], lkey[1]);
    }
    __syncthreads();

    // ---- sort 16 candidates descending by S ----
    if (tid < NCAND) {
        unsigned long long mykey = s_cand[tid];
        int rank = 0;
        for (int j = 0; j < NCAND; ++j) rank += (s_cand[j] > mykey);
        s_p[rank] = (int)(mykey & 8191ULL);
    }
    __syncthreads();

    const int c = tid >> 2, q = tid & 3;
    const float4* Wc  = (const float4*)(W + ((size_t)s * NC + c) * 512) + q * 32;
    const float4* xp4 = (const float4*)xpatch + q * 32;

    // ---- candidate 0 (peeled): exact matvec + Sw/Bn accumulation ----
    {
        int p = s_p[0], t = p >> 4, f = p & 15;
        xpatch[tid] = tile[(t + (tid >> 4)) * TP + f + (tid & 15)];
        __syncthreads();
        float a = 0.f, wsum = 0.f, wsq = 0.f;
        #pragma unroll 8
        for (int i = 0; i < 32; ++i) {
            float4 w = Wc[i], x = xp4[i];
            a = fmaf(w.x, x.x, a); a = fmaf(w.y, x.y, a);
            a = fmaf(w.z, x.z, a); a = fmaf(w.w, x.w, a);
            wsum += (w.x + w.y) + (w.z + w.w);
            wsq  += (w.x*w.x + w.y*w.y) + (w.z*w.z + w.w*w.w);
        }
        a    += __shfl_xor_sync(~0u, a, 1);    a    += __shfl_xor_sync(~0u, a, 2);
        wsum += __shfl_xor_sync(~0u, wsum, 1); wsum += __shfl_xor_sync(~0u, wsum, 2);
        wsq  += __shfl_xor_sync(~0u, wsq, 1);  wsq  += __shfl_xor_sync(~0u, wsq, 2);
        if (q == 0) {
            s_cw[c] = wsum;
            s_cb[c] = sqrtf(fmaxf(wsq - wsum*wsum*(1.0f/512.0f), 0.f));
            if (a >= THR) {
                atomicOr(&s_pool[c >> 5], 1u << (c & 31));
                atomicOr(&s_res[c >> 5],  1u << (c & 31));
            }
        }
        __syncthreads();
    }

    // ---- candidates 1..15: exact matvec for unresolved channels ----
    for (int k = 1; k < NCAND; ++k) {
        if ((s_res[0] & s_res[1] & s_res[2] & s_res[3]) == 0xffffffffu) break;
        int p = s_p[k], t = p >> 4, f = p & 15;
        xpatch[tid] = tile[(t + (tid >> 4)) * TP + f + (tid & 15)];
        __syncthreads();
        bool mine = ((s_res[c >> 5] >> (c & 31)) & 1u) == 0u;
        unsigned m = __ballot_sync(0xffffffffu, mine);
        if (mine) {
            float a = 0.f;
            #pragma unroll 8
            for (int i = 0; i < 32; ++i) {
                float4 w = Wc[i], x = xp4[i];
                a = fmaf(w.x, x.x, a); a = fmaf(w.y, x.y, a);
                a = fmaf(w.z, x.z, a); a = fmaf(w.w, x.w, a);
            }
            a += __shfl_xor_sync(m, a, 1);
            a += __shfl_xor_sync(m, a, 2);
            if (q == 0 && a >= THR) {
                atomicOr(&s_pool[c >> 5], 1u << (c & 31));
                atomicOr(&s_res[c >> 5],  1u << (c & 31));
            }
        }
        __syncthreads();
    }

    // ---- rigorous rare path: CTA-parallel scan per unresolved channel ----
    if ((s_res[0] & s_res[1] & s_res[2] & s_res[3]) != 0xffffffffu) {
        if (tid < NC && !((s_res[tid >> 5] >> (tid & 31)) & 1u))
            s_rem[atomicAdd(&s_rcnt, 1)] = tid;
        __syncthreads();
        const int wid = tid >> 5, lane = tid & 31;
        for (int ri = 0; ri < s_rcnt; ++ri) {
            if (tid == 0) s_cfired = 0;
            __syncthreads();
            const int cc = s_rem[ri];
            const float cw = s_cw[cc], cb = s_cb[cc];
            const float* Wrow = W + ((size_t)s * NC + cc) * 512;
            volatile int* cf = &s_cfired;
            int fired = 0;
            for (int p0 = wid * 400; p0 < wid * 400 + 400 && !fired && !*cf; p0 += 32) {
                int p = p0 + lane;
                float S  = Sarr[p];
                float sn = sqrtf(fmaxf(X2arr[p] - S*S*(1.0f/512.0f), 0.f));
                float base = cw * S * (1.0f/512.0f);
                bool fl  = (base - cb*sn >= THR + MARGIN);
                bool amb = !fl && (base + cb*sn >= THR - MARGIN);
                if (__ballot_sync(~0u, fl)) fired = 1;
                unsigned am = __ballot_sync(~0u, amb);
                while (am && !fired) {
                    int l = __ffs(am) - 1; am &= am - 1;
                    int pp = __shfl_sync(~0u, p, l);
                    int t = pp >> 4, f = pp & 15;
                    const float* wr = Wrow + lane * 16;
                    const float* xr = tile + (t + lane) * TP + f;
                    float a = 0.f;
                    #pragma unroll
                    for (int i = 0; i < 16; ++i) a = fmaf(wr[i], xr[i], a);
                    #pragma unroll
                    for (int d = 16; d; d >>= 1) a += __shfl_xor_sync(~0u, a, d);
                    if (a >= THR) fired = 1;
                }
            }
            if (fired && lane == 0) {
                atomicOr(&s_pool[cc >> 5], 1u << (cc & 31));
                s_cfired = 1;
            }
            __syncthreads();
        }
    }
    __syncthreads();

    if (tid < NC)
        g_pool[(s * NFW + fwin) * NC + tid] =
            (int)((s_pool[tid >> 5] >> (tid & 31)) & 1u);

    // ---- fused winner reduction (last CTA) ----
    __threadfence();
    __syncthreads();
    if (tid == 0) s_last = (atomicAdd(&g_done, 1u) == gridDim.x - 1u);
    __syncthreads();
    if (!s_last) return;
    __threadfence();

    unsigned char* mbuf = (unsigned char*)sm;
    if (tid == 0) { s_any = 0; s_key = -1; }
    __syncthreads();

    int localany = 0;
    for (int cell = tid; cell < NC * NFW; cell += 512) {
        int cc = cell / NFW, f = cell % NFW;
        unsigned mask = 0; int cnt = 0;
        #pragma unroll
        for (int ss = 0; ss < NS; ++ss) {
            int b = g_pool[(ss * NFW + f) * NC + cc];
            mask |= (unsigned)b << ss; cnt += b;
        }
        int e = 8 - cnt; e = e < 0 ? 0 : (e > 7 ? 7 : e);
        int val = (int)((mask >> e) & 1u);
        mbuf[cell] = (unsigned char)((cnt << 1) | val);
        if (cnt > 0 && val > 0) localany = 1;
    }
    if (localany) atomicOr(&s_any, 1);
    __syncthreads();

    const int v = s_any * 8;
    for (int cell = tid; cell < NC * NFW; cell += 512) {
        int d = mbuf[cell];
        int total = (d >> 1) * ((d & 1) + v);
        atomicMax(&s_key, (total << 11) | (2047 - cell));
    }
    __syncthreads();

    if (tid == 0) {
        int key = s_key, total = key >> 11, cell = 2047 - (key & 2047);
        out[0] = total ? (cell / NFW) : -1;
        g_done = 0;
    }
}

extern "C" void kernel_launch(void* const* d_in, const int* in_sizes, int n_in,
                              void* d_out, int out_size)
{
    (void)n_in; (void)out_size;
    const float* X = (const float*)d_in[0];
    const float* W = (const float*)d_in[1];
    if (in_sizes[0] == NS * NC * KT * KF) { const float* t = X; X = W; W = t; }

    const size_t smem = (size_t)SMEM_F * sizeof(float);
    cudaFuncSetAttribute(spyke_kernel,
                         cudaFuncAttributeMaxDynamicSharedMemorySize, (int)smem);
    spyke_kernel<<<NS * NFW, 512, smem>>>(X, W, (int*)d_out);
}

// round 8
// speedup vs baseline: 1.7961x; 1.7961x over previous
#include <cuda_runtime.h>

#define NS 8
#define NC 128
#define KT 32
#define KF 16
#define FREQ 256
#define NFW 15
#define THR 15.0f
#define LPRE 431
#define NPOT 6400
#define MARGIN 0.05f
#define NCAND 16

#define TP 33
#define RP 17
#define RROW_OFF  14224
#define RROW2_OFF 21552
#define S_OFF     28880
#define X2_OFF    35280
#define XP_OFF    41680
#define SMEM_F    42192   /* 168,768 bytes */

__device__ int      g_pool[NS * NFW * NC];
__device__ unsigned g_done;

__global__ __launch_bounds__(512, 1)
void spyke_kernel(const float* __restrict__ X, const float* __restrict__ W,
                  int* __restrict__ out)
{
    extern __shared__ float sm[];
    float* tile   = sm;
    float* Rrow   = sm + RROW_OFF;
    float* Rrow2  = sm + RROW2_OFF;
    float* Sarr   = sm + S_OFF;
    float* X2arr  = sm + X2_OFF;
    float* xpatch = sm + XP_OFF;

    __shared__ unsigned long long s_cand[NCAND];
    __shared__ int s_p[NCAND];
    __shared__ float s_cw[NC], s_cb[NC];
    __shared__ unsigned s_pool[4], s_res[4];
    __shared__ int s_sig_i, s_rcnt, s_last, s_any, s_key, s_cfired;
    __shared__ int s_rem[NC];

    const int s = blockIdx.x / NFW, fwin = blockIdx.x % NFW;
    const int tid = threadIdx.x, col0 = fwin * 16, sec = s * 400;
    const int lane = tid & 31, wid = tid >> 5;

    if (tid < NCAND) s_cand[tid] = 0ULL;
    if (tid < 4) { s_pool[tid] = 0u; s_res[tid] = 0u; }
    if (tid == 0) { s_rcnt = 0; s_sig_i = 0; }

    // ---- stage X window ----
    for (int i = tid; i < LPRE * 31; i += 512) {
        int r = i / 31, c = i - r * 31;
        tile[r * TP + c] = X[(sec + r) * FREQ + col0 + c];
    }
    __syncthreads();

    // ---- row sliding sums/sumsq over kf-window of 16 (pitch 17) ----
    if (tid < LPRE) {
        float a = 0.f, a2 = 0.f;
        for (int c = 0; c < 16; ++c) { float x = tile[tid*TP + c]; a += x; a2 += x*x; }
        Rrow[tid*RP] = a; Rrow2[tid*RP] = a2;
        for (int f = 1; f < 16; ++f) {
            float xo = tile[tid*TP + f - 1], xn = tile[tid*TP + f + 15];
            a += xn - xo; a2 += xn*xn - xo*xo;
            Rrow[tid*RP + f] = a; Rrow2[tid*RP + f] = a2;
        }
    }
    __syncthreads();

    // ---- column sliding over kt-window of 32 (conflict-free: f = tid%16) ----
    if (tid < 320) {
        int f = tid & 15, t0 = (tid >> 4) * 20;
        float a = 0.f, a2 = 0.f;
        for (int k = 0; k < 32; ++k) { a += Rrow[(t0+k)*RP+f]; a2 += Rrow2[(t0+k)*RP+f]; }
        unsigned long long lkey[2] = {0ULL, 0ULL};
        int reg0 = t0 / 25;
        float lsig = 0.f;
        for (int t = t0; t < t0 + 20; ++t) {
            int p = t*16 + f;
            Sarr[p] = a; X2arr[p] = a2;
            lsig = fmaxf(lsig, a2 - a*a*(1.0f/512.0f));
            unsigned long long key =
                ((unsigned long long)__float_as_uint(a) << 13) | (unsigned)p;
            int ri = (t / 25) - reg0;
            if (key > lkey[ri]) lkey[ri] = key;
            if (t <= 398) {
                a  += Rrow[(t+32)*RP+f]  - Rrow[t*RP+f];
                a2 += Rrow2[(t+32)*RP+f] - Rrow2[t*RP+f];
            }
        }
        atomicMax(&s_cand[reg0], lkey[0]);
        if (lkey[1] && reg0 + 1 < NCAND) atomicMax(&s_cand[reg0 + 1], lkey[1]);
        atomicMax(&s_sig_i, __float_as_int(fmaxf(lsig, 0.f)));
    }
    __syncthreads();

    // ---- sort 16 candidates descending by S ----
    if (tid < NCAND) {
        unsigned long long mykey = s_cand[tid];
        int rank = 0;
        for (int j = 0; j < NCAND; ++j) rank += (s_cand[j] > mykey);
        s_p[rank] = (int)(mykey & 8191ULL);
    }
    __syncthreads();

    const float4* Ws  = (const float4*)(W + (size_t)s * NC * 512);
    const float4* xp4 = (const float4*)xpatch;

    // ---- candidate probes: warp-per-channel coalesced matvec ----
    for (int k = 0; k < NCAND; ++k) {
        int p = s_p[k], t = p >> 4, f = p & 15;
        xpatch[tid] = tile[(t + (tid >> 4)) * TP + f + (tid & 15)];
        __syncthreads();
        float x0x = xp4[lane].x,      x0y = xp4[lane].y,      x0z = xp4[lane].z,      x0w = xp4[lane].w;
        float x1x = xp4[lane+32].x,   x1y = xp4[lane+32].y,   x1z = xp4[lane+32].z,   x1w = xp4[lane+32].w;
        float x2x = xp4[lane+64].x,   x2y = xp4[lane+64].y,   x2z = xp4[lane+64].z,   x2w = xp4[lane+64].w;
        float x3x = xp4[lane+96].x,   x3y = xp4[lane+96].y,   x3z = xp4[lane+96].z,   x3w = xp4[lane+96].w;
        #pragma unroll
        for (int j = 0; j < 8; ++j) {
            int c = wid * 8 + j;
            if (k > 0 && ((s_res[c >> 5] >> (c & 31)) & 1u)) continue;
            const float4* Wc = Ws + (size_t)c * 128;
            float4 w0 = Wc[lane], w1 = Wc[lane+32], w2 = Wc[lane+64], w3 = Wc[lane+96];
            float a = 0.f;
            a = fmaf(w0.x, x0x, a); a = fmaf(w0.y, x0y, a); a = fmaf(w0.z, x0z, a); a = fmaf(w0.w, x0w, a);
            a = fmaf(w1.x, x1x, a); a = fmaf(w1.y, x1y, a); a = fmaf(w1.z, x1z, a); a = fmaf(w1.w, x1w, a);
            a = fmaf(w2.x, x2x, a); a = fmaf(w2.y, x2y, a); a = fmaf(w2.z, x2z, a); a = fmaf(w2.w, x2w, a);
            a = fmaf(w3.x, x3x, a); a = fmaf(w3.y, x3y, a); a = fmaf(w3.z, x3z, a); a = fmaf(w3.w, x3w, a);
            if (k == 0) {
                float ws = (w0.x+w0.y+w0.z+w0.w) + (w1.x+w1.y+w1.z+w1.w)
                         + (w2.x+w2.y+w2.z+w2.w) + (w3.x+w3.y+w3.z+w3.w);
                float wq = (w0.x*w0.x+w0.y*w0.y+w0.z*w0.z+w0.w*w0.w)
                         + (w1.x*w1.x+w1.y*w1.y+w1.z*w1.z+w1.w*w1.w)
                         + (w2.x*w2.x+w2.y*w2.y+w2.z*w2.z+w2.w*w2.w)
                         + (w3.x*w3.x+w3.y*w3.y+w3.z*w3.z+w3.w*w3.w);
                #pragma unroll
                for (int d = 16; d; d >>= 1) {
                    a  += __shfl_xor_sync(~0u, a,  d);
                    ws += __shfl_xor_sync(~0u, ws, d);
                    wq += __shfl_xor_sync(~0u, wq, d);
                }
                if (lane == 0) {
                    s_cw[c] = ws;
                    s_cb[c] = sqrtf(fmaxf(wq - ws*ws*(1.0f/512.0f), 0.f));
                }
            } else {
                #pragma unroll
                for (int d = 16; d; d >>= 1) a += __shfl_xor_sync(~0u, a, d);
            }
            if (lane == 0 && a >= THR) {
                atomicOr(&s_pool[c >> 5], 1u << (c & 31));
                atomicOr(&s_res[c >> 5],  1u << (c & 31));
            }
        }
        __syncthreads();
        if ((s_res[0] & s_res[1] & s_res[2] & s_res[3]) == 0xffffffffu) break;
    }

    // ---- rigorous rare path for unresolved channels ----
    if ((s_res[0] & s_res[1] & s_res[2] & s_res[3]) != 0xffffffffu) {
        const float Smax   = Sarr[s_p[0]];
        const float sigMax = sqrtf(__int_as_float(s_sig_i));
        // global kill: channel provably below THR everywhere
        if (tid < NC && !((s_res[tid >> 5] >> (tid & 31)) & 1u)) {
            if (s_cw[tid] * Smax * (1.0f/512.0f) + s_cb[tid] * sigMax < THR - MARGIN)
                ; /* dead: pool stays 0 */
            else
                s_rem[atomicAdd(&s_rcnt, 1)] = tid;
        }
        __syncthreads();
        for (int ri = 0; ri < s_rcnt; ++ri) {
            if (tid == 0) s_cfired = 0;
            __syncthreads();
            const int cc = s_rem[ri];
            const float cw = s_cw[cc], cb = s_cb[cc];
            const float* Wrow = W + ((size_t)s * NC + cc) * 512;
            volatile int* cf = &s_cfired;
            int fired = 0;
            for (int p0 = wid * 400; p0 < wid * 400 + 400 && !fired && !*cf; p0 += 32) {
                int p = p0 + lane;
                float S  = Sarr[p];
                float sn = sqrtf(fmaxf(X2arr[p] - S*S*(1.0f/512.0f), 0.f));
                float base = cw * S * (1.0f/512.0f);
                bool fl  = (base - cb*sn >= THR + MARGIN);
                bool amb = !fl && (base + cb*sn >= THR - MARGIN);
                if (__ballot_sync(~0u, fl)) fired = 1;
                unsigned am = __ballot_sync(~0u, amb);
                while (am && !fired) {
                    int l = __ffs(am) - 1; am &= am - 1;
                    int pp = __shfl_sync(~0u, p, l);
                    int t = pp >> 4, f = pp & 15;
                    const float* wr = Wrow + lane * 16;
                    const float* xr = tile + (t + lane) * TP + f;
                    float a = 0.f;
                    #pragma unroll
                    for (int i = 0; i < 16; ++i) a = fmaf(wr[i], xr[i], a);
                    #pragma unroll
                    for (int d = 16; d; d >>= 1) a += __shfl_xor_sync(~0u, a, d);
                    if (a >= THR) fired = 1;
                }
            }
            if (fired && lane == 0) {
                atomicOr(&s_pool[cc >> 5], 1u << (cc & 31));
                s_cfired = 1;
            }
            __syncthreads();
        }
    }
    __syncthreads();

    if (tid < NC)
        g_pool[(s * NFW + fwin) * NC + tid] =
            (int)((s_pool[tid >> 5] >> (tid & 31)) & 1u);

    // ---- fused winner reduction (last CTA) ----
    __threadfence();
    __syncthreads();
    if (tid == 0) s_last = (atomicAdd(&g_done, 1u) == gridDim.x - 1u);
    __syncthreads();
    if (!s_last) return;
    __threadfence();

    unsigned char* mbuf = (unsigned char*)sm;
    if (tid == 0) { s_any = 0; s_key = -1; }
    __syncthreads();

    int localany = 0;
    for (int cell = tid; cell < NC * NFW; cell += 512) {
        int cc = cell / NFW, f = cell % NFW;
        unsigned mask = 0; int cnt = 0;
        #pragma unroll
        for (int ss = 0; ss < NS; ++ss) {
            int b = g_pool[(ss * NFW + f) * NC + cc];
            mask |= (unsigned)b << ss; cnt += b;
        }
        int e = 8 - cnt; e = e < 0 ? 0 : (e > 7 ? 7 : e);
        int val = (int)((mask >> e) & 1u);
        mbuf[cell] = (unsigned char)((cnt << 1) | val);
        if (cnt > 0 && val > 0) localany = 1;
    }
    if (localany) atomicOr(&s_any, 1);
    __syncthreads();

    const int v = s_any * 8;
    for (int cell = tid; cell < NC * NFW; cell += 512) {
        int d = mbuf[cell];
        int total = (d >> 1) * ((d & 1) + v);
        atomicMax(&s_key, (total << 11) | (2047 - cell));
    }
    __syncthreads();

    if (tid == 0) {
        int key = s_key, total = key >> 11, cell = 2047 - (key & 2047);
        out[0] = total ? (cell / NFW) : -1;
        g_done = 0;
    }
}

extern "C" void kernel_launch(void* const* d_in, const int* in_sizes, int n_in,
                              void* d_out, int out_size)
{
    (void)n_in; (void)out_size;
    const float* X = (const float*)d_in[0];
    const float* W = (const float*)d_in[1];
    if (in_sizes[0] == NS * NC * KT * KF) { const float* t = X; X = W; W = t; }

    const size_t smem = (size_t)SMEM_F * sizeof(float);
    cudaFuncSetAttribute(spyke_kernel,
                         cudaFuncAttributeMaxDynamicSharedMemorySize, (int)smem);
    spyke_kernel<<<NS * NFW, 512, smem>>>(X, W, (int*)d_out);
}

// round 9
// speedup vs baseline: 2.4697x; 1.3750x over previous
#include <cuda_runtime.h>

#define NS 8
#define NC 128
#define KT 32
#define KF 16
#define FREQ 256
#define NFW 15
#define THR 15.0f
#define LPRE 431
#define NPOT 6400
#define MARGIN 0.05f
#define NCAND 16

#define TP 33
#define RP 17
#define RROW_OFF  14224          /* tile = 431*33 = 14223 */
#define S_OFF     21552          /* Rrow = 431*17 = 7327 -> 7328 */
#define X2_OFF    27952          /* lazy */
#define RROW2_OFF 34352          /* lazy */
#define XP_OFF    41680
#define SMEM_F    42192          /* 168,768 bytes */

__device__ unsigned g_poolw[NS * NFW * 4];
__device__ unsigned g_done;

__global__ __launch_bounds__(512, 1)
void spyke_kernel(const float* __restrict__ X, const float* __restrict__ W,
                  int* __restrict__ out)
{
    extern __shared__ float sm[];
    float* tile   = sm;
    float* Rrow   = sm + RROW_OFF;
    float* Sarr   = sm + S_OFF;
    float* X2arr  = sm + X2_OFF;
    float* Rrow2  = sm + RROW2_OFF;
    float* xpatch = sm + XP_OFF;

    __shared__ unsigned long long s_cand[NCAND];
    __shared__ int s_p[NCAND];
    __shared__ float s_cw[NC], s_cb[NC];
    __shared__ unsigned s_pool[4], s_res[4];
    __shared__ int s_sig_i, s_rcnt, s_last, s_any, s_key, s_cfired;
    __shared__ int s_rem[NC];

    const int s = blockIdx.x / NFW, fwin = blockIdx.x % NFW;
    const int tid = threadIdx.x, col0 = fwin * 16, sec = s * 400;
    const int lane = tid & 31, wid = tid >> 5;

    if (tid < NCAND) s_cand[tid] = 0ULL;
    if (tid < 4) { s_pool[tid] = 0u; s_res[tid] = 0u; }
    if (tid == 0) { s_rcnt = 0; s_sig_i = 0; }

    // ---- stage X window ----
    for (int i = tid; i < LPRE * 31; i += 512) {
        int r = i / 31, c = i - r * 31;
        tile[r * TP + c] = X[(sec + r) * FREQ + col0 + c];
    }
    __syncthreads();

    // ---- row sliding sums over kf-window of 16 (pitch 17) ----
    if (tid < LPRE) {
        float a = 0.f;
        #pragma unroll
        for (int c = 0; c < 16; ++c) a += tile[tid*TP + c];
        Rrow[tid*RP] = a;
        #pragma unroll 5
        for (int f = 1; f < 16; ++f) {
            a += tile[tid*TP + f + 15] - tile[tid*TP + f - 1];
            Rrow[tid*RP + f] = a;
        }
    }
    __syncthreads();

    // ---- column sliding over kt-window of 32: S + per-region argmax ----
    if (tid < 400) {
        int f = tid & 15, t0 = (tid >> 4) * 16;
        float a = 0.f;
        #pragma unroll 8
        for (int k = 0; k < 32; ++k) a += Rrow[(t0+k)*RP+f];
        unsigned long long lkey[2] = {0ULL, 0ULL};
        int reg0 = t0 / 25;
        for (int t = t0; t < t0 + 16; ++t) {
            int p = t*16 + f;
            Sarr[p] = a;
            unsigned long long key =
                ((unsigned long long)__float_as_uint(a) << 13) | (unsigned)p;
            int ri = (t / 25) - reg0;
            if (key > lkey[ri]) lkey[ri] = key;
            if (t <= 398) a += Rrow[(t+32)*RP+f] - Rrow[t*RP+f];
        }
        atomicMax(&s_cand[reg0], lkey[0]);
        if (lkey[1] && reg0 + 1 < NCAND) atomicMax(&s_cand[reg0 + 1], lkey[1]);
    }
    __syncthreads();

    // ---- sort candidates descending ----
    if (tid < NCAND) {
        unsigned long long mykey = s_cand[tid];
        int rank = 0;
        for (int j = 0; j < NCAND; ++j) rank += (s_cand[j] > mykey);
        s_p[rank] = (int)(mykey & 8191ULL);
    }
    __syncthreads();

    const float4* Ws  = (const float4*)(W + (size_t)s * NC * 512);
    const float4* xp4 = (const float4*)xpatch;

    // ---- candidate probes: warp-per-channel coalesced matvec ----
    for (int k = 0; k < NCAND; ++k) {
        int p = s_p[k], t = p >> 4, f = p & 15;
        xpatch[tid] = tile[(t + (tid >> 4)) * TP + f + (tid & 15)];
        __syncthreads();
        float4 xq0 = xp4[lane], xq1 = xp4[lane+32], xq2 = xp4[lane+64], xq3 = xp4[lane+96];
        #pragma unroll
        for (int j = 0; j < 8; ++j) {
            int c = wid * 8 + j;
            if (k > 0 && ((s_res[c >> 5] >> (c & 31)) & 1u)) continue;
            const float4* Wc = Ws + (size_t)c * 128;
            float4 w0 = Wc[lane], w1 = Wc[lane+32], w2 = Wc[lane+64], w3 = Wc[lane+96];
            float a = 0.f;
            a = fmaf(w0.x, xq0.x, a); a = fmaf(w0.y, xq0.y, a); a = fmaf(w0.z, xq0.z, a); a = fmaf(w0.w, xq0.w, a);
            a = fmaf(w1.x, xq1.x, a); a = fmaf(w1.y, xq1.y, a); a = fmaf(w1.z, xq1.z, a); a = fmaf(w1.w, xq1.w, a);
            a = fmaf(w2.x, xq2.x, a); a = fmaf(w2.y, xq2.y, a); a = fmaf(w2.z, xq2.z, a); a = fmaf(w2.w, xq2.w, a);
            a = fmaf(w3.x, xq3.x, a); a = fmaf(w3.y, xq3.y, a); a = fmaf(w3.z, xq3.z, a); a = fmaf(w3.w, xq3.w, a);
            #pragma unroll
            for (int d = 16; d; d >>= 1) a += __shfl_xor_sync(~0u, a, d);
            if (lane == 0 && a >= THR) {
                atomicOr(&s_pool[c >> 5], 1u << (c & 31));
                atomicOr(&s_res[c >> 5],  1u << (c & 31));
            }
        }
        __syncthreads();
        if ((s_res[0] & s_res[1] & s_res[2] & s_res[3]) == 0xffffffffu) break;
    }

    // ================= rigorous cold path (lazy stats) =================
    if ((s_res[0] & s_res[1] & s_res[2] & s_res[3]) != 0xffffffffu) {
        // recompute sumsq rows
        if (tid < LPRE) {
            float a2 = 0.f;
            #pragma unroll
            for (int c = 0; c < 16; ++c) { float x = tile[tid*TP + c]; a2 += x*x; }
            Rrow2[tid*RP] = a2;
            for (int f = 1; f < 16; ++f) {
                float xo = tile[tid*TP + f - 1], xn = tile[tid*TP + f + 15];
                a2 += xn*xn - xo*xo;
                Rrow2[tid*RP + f] = a2;
            }
        }
        __syncthreads();
        if (tid < 400) {
            int f = tid & 15, t0 = (tid >> 4) * 16;
            float a2 = 0.f;
            for (int k = 0; k < 32; ++k) a2 += Rrow2[(t0+k)*RP+f];
            float lsig = 0.f;
            for (int t = t0; t < t0 + 16; ++t) {
                int p = t*16 + f;
                X2arr[p] = a2;
                float S = Sarr[p];
                lsig = fmaxf(lsig, a2 - S*S*(1.0f/512.0f));
                if (t <= 398) a2 += Rrow2[(t+32)*RP+f] - Rrow2[t*RP+f];
            }
            atomicMax(&s_sig_i, __float_as_int(fmaxf(lsig, 0.f)));
        }
        __syncthreads();

        // per-channel Sw / Bn for unresolved channels (warp per channel)
        for (int c = wid; c < NC; c += 16) {
            if ((s_res[c >> 5] >> (c & 31)) & 1u) continue;
            const float4* Wc = Ws + (size_t)c * 128;
            float4 w0 = Wc[lane], w1 = Wc[lane+32], w2 = Wc[lane+64], w3 = Wc[lane+96];
            float ws = (w0.x+w0.y+w0.z+w0.w) + (w1.x+w1.y+w1.z+w1.w)
                     + (w2.x+w2.y+w2.z+w2.w) + (w3.x+w3.y+w3.z+w3.w);
            float wq = (w0.x*w0.x+w0.y*w0.y+w0.z*w0.z+w0.w*w0.w)
                     + (w1.x*w1.x+w1.y*w1.y+w1.z*w1.z+w1.w*w1.w)
                     + (w2.x*w2.x+w2.y*w2.y+w2.z*w2.z+w2.w*w2.w)
                     + (w3.x*w3.x+w3.y*w3.y+w3.z*w3.z+w3.w*w3.w);
            #pragma unroll
            for (int d = 16; d; d >>= 1) {
                ws += __shfl_xor_sync(~0u, ws, d);
                wq += __shfl_xor_sync(~0u, wq, d);
            }
            if (lane == 0) {
                s_cw[c] = ws;
                s_cb[c] = sqrtf(fmaxf(wq - ws*ws*(1.0f/512.0f), 0.f));
            }
        }
        __syncthreads();

        const float Smax   = Sarr[s_p[0]];
        const float sigMax = sqrtf(__int_as_float(s_sig_i));
        if (tid < NC && !((s_res[tid >> 5] >> (tid & 31)) & 1u)) {
            if (s_cw[tid] * Smax * (1.0f/512.0f) + s_cb[tid] * sigMax >= THR - MARGIN)
                s_rem[atomicAdd(&s_rcnt, 1)] = tid;   /* else provably never fires */
        }
        __syncthreads();

        for (int ri = 0; ri < s_rcnt; ++ri) {
            if (tid == 0) s_cfired = 0;
            __syncthreads();
            const int cc = s_rem[ri];
            const float cw = s_cw[cc], cb = s_cb[cc];
            const float* Wrow = W + ((size_t)s * NC + cc) * 512;
            volatile int* cf = &s_cfired;
            int fired = 0;
            for (int p0 = wid * 400; p0 < wid * 400 + 400 && !fired && !*cf; p0 += 32) {
                int p = p0 + lane;
                float S  = Sarr[p];
                float sn = sqrtf(fmaxf(X2arr[p] - S*S*(1.0f/512.0f), 0.f));
                float base = cw * S * (1.0f/512.0f);
                bool fl  = (base - cb*sn >= THR + MARGIN);
                bool amb = !fl && (base + cb*sn >= THR - MARGIN);
                if (__ballot_sync(~0u, fl)) fired = 1;
                unsigned am = __ballot_sync(~0u, amb);
                while (am && !fired) {
                    int l = __ffs(am) - 1; am &= am - 1;
                    int pp = __shfl_sync(~0u, p, l);
                    int t = pp >> 4, f = pp & 15;
                    const float* wr = Wrow + lane * 16;
                    const float* xr = tile + (t + lane) * TP + f;
                    float a = 0.f;
                    #pragma unroll
                    for (int i = 0; i < 16; ++i) a = fmaf(wr[i], xr[i], a);
                    #pragma unroll
                    for (int d = 16; d; d >>= 1) a += __shfl_xor_sync(~0u, a, d);
                    if (a >= THR) fired = 1;
                }
            }
            if (fired && lane == 0) {
                atomicOr(&s_pool[cc >> 5], 1u << (cc & 31));
                s_cfired = 1;
            }
            __syncthreads();
        }
    }
    __syncthreads();

    if (tid < 4)
        g_poolw[(s * NFW + fwin) * 4 + tid] = s_pool[tid];

    // ---- fused winner reduction (last CTA) ----
    __threadfence();
    __syncthreads();
    if (tid == 0) s_last = (atomicAdd(&g_done, 1u) == gridDim.x - 1u);
    __syncthreads();
    if (!s_last) return;
    __threadfence();

    unsigned char* mbuf = (unsigned char*)sm;
    if (tid == 0) { s_any = 0; s_key = -1; }
    __syncthreads();

    int localany = 0;
    for (int cell = tid; cell < NC * NFW; cell += 512) {
        int cc = cell / NFW, f = cell % NFW;
        int wword = cc >> 5, wbit = cc & 31;
        unsigned mask = 0; int cnt = 0;
        #pragma unroll
        for (int ss = 0; ss < NS; ++ss) {
            int b = (int)((g_poolw[(ss * NFW + f) * 4 + wword] >> wbit) & 1u);
            mask |= (unsigned)b << ss; cnt += b;
        }
        int e = 8 - cnt; e = e < 0 ? 0 : (e > 7 ? 7 : e);
        int val = (int)((mask >> e) & 1u);
        mbuf[cell] = (unsigned char)((cnt << 1) | val);
        if (cnt > 0 && val > 0) localany = 1;
    }
    if (localany) atomicOr(&s_any, 1);
    __syncthreads();

    const int v = s_any * 8;
    for (int cell = tid; cell < NC * NFW; cell += 512) {
        int d = mbuf[cell];
        int total = (d >> 1) * ((d & 1) + v);
        atomicMax(&s_key, (total << 11) | (2047 - cell));
    }
    __syncthreads();

    if (tid == 0) {
        int key = s_key, total = key >> 11, cell = 2047 - (key & 2047);
        out[0] = total ? (cell / NFW) : -1;
        g_done = 0;
    }
}

extern "C" void kernel_launch(void* const* d_in, const int* in_sizes, int n_in,
                              void* d_out, int out_size)
{
    (void)n_in; (void)out_size;
    const float* X = (const float*)d_in[0];
    const float* W = (const float*)d_in[1];
    if (in_sizes[0] == NS * NC * KT * KF) { const float* t = X; X = W; W = t; }

    const size_t smem = (size_t)SMEM_F * sizeof(float);
    cudaFuncSetAttribute(spyke_kernel,
                         cudaFuncAttributeMaxDynamicSharedMemorySize, (int)smem);
    spyke_kernel<<<NS * NFW, 512, smem>>>(X, W, (int*)d_out);
}